// round 9
// baseline (speedup 1.0000x reference)
#include <cuda_runtime.h>
#include <cstdint>

#define NB 16
#define NF 6
#define NPIX 262144
#define NP4 (NPIX / 4)   // 65536 float4 per (b,f)
#define NK 8
#define NKK 4            // packed k-pairs
#define NITERS 12
#define NCH 27           // chunks per batch -> grid 432 (~3 CTAs/SM)
#define SPLIT 8          // blocks per (b,f) in stats kernel
#define NSLOT 56         // NK*(NF+1) partial-sum slots
#define THREADS 128      // 4 warps/CTA, 3 CTAs/SM = 12 warps in 3 barrier domains
#define NWARP (THREADS / 32)
#define STG4 256         // float4s per pipeline stage (per f) = 2/thread
#define NBUF 3           // pipeline depth

typedef unsigned long long u64p;   // packed f32x2 (and cache policy)
typedef unsigned int u32;

// Dynamic smem layout (bytes)
#define BUFB   (NBUF * NF * STG4 * 16)      // 73728
#define MBAR_O (BUFB)                       // 3 mbarriers (24B, pad 32)
#define GH_O   (BUFB + 32)                  // s_g[48] + s_h[8] floats
#define RED_O  (BUFB + 32 + 224)            // float[NWARP][NSLOT]
#define SMEMSZ (RED_O + NWARP * NSLOT * 4)  // ~74.8 KB -> 3 CTAs/SM

// Scratch (static __device__ — no allocations allowed)
__device__ float d_statpart[NB * NF * SPLIT * 2];
__device__ float d_mean[NB * NF];
__device__ float d_sinv[NB * NF];
__device__ float d_g[NB * NK * NF];   // folded centroid weights (init only)
__device__ float d_h[NB * NK];        // folded centroid bias   (init only)
__device__ float d_part[NB * NCH * NSLOT];

__device__ __forceinline__ float ex2f(float x) {
    float y; asm("ex2.approx.ftz.f32 %0, %1;" : "=f"(y) : "f"(x)); return y;
}
__device__ __forceinline__ float rcpf(float x) {
    float y; asm("rcp.approx.ftz.f32 %0, %1;" : "=f"(y) : "f"(x)); return y;
}
// ---- packed f32x2 helpers (FFMA2 etc — only reachable via PTX) ----
__device__ __forceinline__ u64p pk2(float lo, float hi) {
    u64p r; asm("mov.b64 %0, {%1, %2};" : "=l"(r) : "f"(lo), "f"(hi)); return r;
}
__device__ __forceinline__ void upk2(u64p v, float& lo, float& hi) {
    asm("mov.b64 {%0, %1}, %2;" : "=f"(lo), "=f"(hi) : "l"(v));
}
__device__ __forceinline__ u64p fma2(u64p a, u64p b, u64p c) {
    u64p d; asm("fma.rn.f32x2 %0, %1, %2, %3;" : "=l"(d) : "l"(a), "l"(b), "l"(c)); return d;
}
__device__ __forceinline__ u64p add2(u64p a, u64p b) {
    u64p d; asm("add.rn.f32x2 %0, %1, %2;" : "=l"(d) : "l"(a), "l"(b)); return d;
}
__device__ __forceinline__ u64p mul2(u64p a, u64p b) {
    u64p d; asm("mul.rn.f32x2 %0, %1, %2;" : "=l"(d) : "l"(a), "l"(b)); return d;
}
// ---- smem / mbarrier / bulk-copy helpers ----
__device__ __forceinline__ u32 smem_u32(const void* p) {
    u32 a;
    asm("{ .reg .u64 t; cvta.to.shared.u64 t, %1; cvt.u32.u64 %0, t; }" : "=r"(a) : "l"(p));
    return a;
}
__device__ __forceinline__ void mbar_init(u32 mbar, u32 cnt) {
    asm volatile("mbarrier.init.shared.b64 [%0], %1;" :: "r"(mbar), "r"(cnt) : "memory");
}
__device__ __forceinline__ void mbar_expect_tx(u32 mbar, u32 bytes) {
    asm volatile("mbarrier.arrive.expect_tx.shared.b64 _, [%0], %1;" :: "r"(mbar), "r"(bytes) : "memory");
}
__device__ __forceinline__ void mbar_wait(u32 mbar, u32 phase) {
    asm volatile(
        "{\n\t.reg .pred P;\n"
        "WL_%=:\n\t"
        "mbarrier.try_wait.parity.acquire.cta.shared::cta.b64 P, [%0], %1, 0x989680;\n\t"
        "@P bra WD_%=;\n\t"
        "bra WL_%=;\n"
        "WD_%=:\n\t}"
        :: "r"(mbar), "r"(phase) : "memory");
}
__device__ __forceinline__ u64p mk_policy() {
    u64p p; asm("createpolicy.fractional.L2::evict_last.b64 %0, 1.0;" : "=l"(p));
    return p;
}
__device__ __forceinline__ void bulk_g2s(u32 dst, const void* src, u32 bytes,
                                         u32 mbar, u64p pol) {
    asm volatile(
        "cp.async.bulk.shared::cluster.global.mbarrier::complete_tx::bytes.L2::cache_hint "
        "[%0], [%1], %2, [%3], %4;"
        :: "r"(dst), "l"(src), "r"(bytes), "r"(mbar), "l"(pol) : "memory");
}

// ---------------------------------------------------------------------------
// Per-(b,f) sum / sumsq partials over pixels
// ---------------------------------------------------------------------------
__global__ __launch_bounds__(256) void stats_kernel(const float* __restrict__ feat) {
    int bf = blockIdx.x >> 3;     // / SPLIT
    int part = blockIdx.x & 7;    // % SPLIT
    const float4* p = ((const float4*)feat) + (size_t)bf * NP4;
    int t = threadIdx.x;
    float s = 0.f, q = 0.f;
    #pragma unroll 8
    for (int i = 0; i < 32; i++) {
        float4 v = p[part * 8192 + i * 256 + t];
        s += (v.x + v.y) + (v.z + v.w);
        q = fmaf(v.x, v.x, q); q = fmaf(v.y, v.y, q);
        q = fmaf(v.z, v.z, q); q = fmaf(v.w, v.w, q);
    }
    #pragma unroll
    for (int o = 16; o; o >>= 1) {
        s += __shfl_xor_sync(0xffffffffu, s, o);
        q += __shfl_xor_sync(0xffffffffu, q, o);
    }
    __shared__ float sm[16];
    if ((t & 31) == 0) { sm[t >> 5] = s; sm[8 + (t >> 5)] = q; }
    __syncthreads();
    if (t == 0) {
        float S = 0.f, Q = 0.f;
        #pragma unroll
        for (int i = 0; i < 8; i++) { S += sm[i]; Q += sm[8 + i]; }
        d_statpart[(bf * SPLIT + part) * 2 + 0] = S;
        d_statpart[(bf * SPLIT + part) * 2 + 1] = Q;
    }
}

// ---------------------------------------------------------------------------
// Finalize mean/invstd; gather initial centroids; fold into (g, h)
// logit_k(pixel) = sum_f u_f * g_kf + h_k   (softmax shift-invariance drops the
// per-pixel x2/T term; log2e folded so exp is a single MUFU ex2)
// ---------------------------------------------------------------------------
__global__ void init_kernel(const float* __restrict__ feat, const int* __restrict__ idx) {
    int t = threadIdx.x;  // 128 = NB*NK
    if (t < NB * NF) {
        float S = 0.f, Q = 0.f;
        for (int i = 0; i < SPLIT; i++) {
            S += d_statpart[(t * SPLIT + i) * 2 + 0];
            Q += d_statpart[(t * SPLIT + i) * 2 + 1];
        }
        float mean = S * (1.f / (float)NPIX);
        float var = (Q - (float)NPIX * mean * mean) * (1.f / (float)(NPIX - 1));
        var = fmaxf(var, 0.f);
        float sd = sqrtf(var);
        d_mean[t] = mean;
        d_sinv[t] = 1.f / fmaxf(sd, 1e-6f);
    }
    __syncthreads();
    int b = t >> 3;
    int n = idx[t];
    const float alpha = 1.4426950408889634f / 0.15f;  // log2(e)/TEMP
    float c2 = 0.f;
    float g[NF];
    #pragma unroll
    for (int f = 0; f < NF; f++) {
        float u = feat[(size_t)(b * NF + f) * NPIX + n];
        float c = (u - d_mean[b * NF + f]) * d_sinv[b * NF + f];
        c2 = fmaf(c, c, c2);
        g[f] = 2.f * alpha * d_sinv[b * NF + f] * c;
    }
    float h = -alpha * c2;
    #pragma unroll
    for (int f = 0; f < NF; f++) {
        h -= d_mean[b * NF + f] * g[f];
        d_g[t * NF + f] = g[f];
    }
    d_h[t] = h;
}

// ---------------------------------------------------------------------------
// Per-block preamble: centroid update from previous pass's partials
// (redundant per block — the launch boundary is the grid sync).
// ---------------------------------------------------------------------------
__device__ __forceinline__ void compute_gh(int b, int do_update, float* s_g, float* s_h) {
    int t = threadIdx.x;
    if (t < NK) {
        int k = t;
        float gg[NF], hh;
        if (do_update) {
            float W = 0.f, A[NF] = {0.f, 0.f, 0.f, 0.f, 0.f, 0.f};
            for (int i = 0; i < NCH; i++) {
                const float* pp = d_part + (size_t)(b * NCH + i) * NSLOT;
                W += pp[48 + k];
                #pragma unroll
                for (int f = 0; f < NF; f++) A[f] += pp[k * NF + f];
            }
            float rW = 1.f / fmaxf(W, 1e-6f);
            const float alpha = 1.4426950408889634f / 0.15f;
            float c2 = 0.f;
            #pragma unroll
            for (int f = 0; f < NF; f++) {
                float si = d_sinv[b * NF + f];
                // C_kf = s_f * (A_f - m_f*W) / clip(W, EPS)  (matches reference)
                float c = si * (A[f] - d_mean[b * NF + f] * W) * rW;
                c2 = fmaf(c, c, c2);
                gg[f] = 2.f * alpha * si * c;
            }
            hh = -alpha * c2;
            #pragma unroll
            for (int f = 0; f < NF; f++) hh -= d_mean[b * NF + f] * gg[f];
        } else {
            #pragma unroll
            for (int f = 0; f < NF; f++) gg[f] = d_g[(b * NK + k) * NF + f];
            hh = d_h[b * NK + k];
        }
        #pragma unroll
        for (int f = 0; f < NF; f++) s_g[k * NF + f] = gg[f];
        s_h[k] = hh;
    }
}

// ---------------------------------------------------------------------------
// Packed softmax core
// ---------------------------------------------------------------------------
__device__ __forceinline__ void softmax_core(const float x[NF],
                                             const u64p g2[NKK][NF], const u64p h2[NKK],
                                             u64p x2[NF], u64p p2[NKK], float& r) {
    #pragma unroll
    for (int f = 0; f < NF; f++) x2[f] = pk2(x[f], x[f]);
    u64p l2[NKK];
    #pragma unroll
    for (int kk = 0; kk < NKK; kk++) l2[kk] = fma2(x2[0], g2[kk][0], h2[kk]);
    #pragma unroll
    for (int f = 1; f < NF; f++)
        #pragma unroll
        for (int kk = 0; kk < NKK; kk++) l2[kk] = fma2(x2[f], g2[kk][f], l2[kk]);
    float l[NK];
    #pragma unroll
    for (int kk = 0; kk < NKK; kk++) upk2(l2[kk], l[2 * kk], l[2 * kk + 1]);
    float m = l[0];
    #pragma unroll
    for (int k = 1; k < NK; k++) m = fmaxf(m, l[k]);
    u64p mn2 = pk2(-m, -m);
    float p[NK];
    #pragma unroll
    for (int kk = 0; kk < NKK; kk++) {
        u64p e = add2(l2[kk], mn2);
        float a, c; upk2(e, a, c);
        p[2 * kk] = ex2f(a);
        p[2 * kk + 1] = ex2f(c);
    }
    #pragma unroll
    for (int kk = 0; kk < NKK; kk++) p2[kk] = pk2(p[2 * kk], p[2 * kk + 1]);
    u64p s2 = add2(add2(p2[0], p2[1]), add2(p2[2], p2[3]));
    float sl, sh; upk2(s2, sl, sh);
    r = rcpf(sl + sh);
}

// ---------------------------------------------------------------------------
// Stage issue: thread 0 prefetches stage s of this chunk into buffer bufi
// ---------------------------------------------------------------------------
__device__ __forceinline__ void issue_stage(const float4* pf, int c0, int nf4, int s,
                                            int bufi, u32 sbase, u32 mbar, u64p pol) {
    int base = s * STG4;
    int n = nf4 - base; if (n > STG4) n = STG4;
    u32 bytes = (u32)n * 16u;
    mbar_expect_tx(mbar, bytes * NF);
    #pragma unroll
    for (int f = 0; f < NF; f++) {
        u32 dst = sbase + (u32)((bufi * NF + f) * STG4) * 16u;
        bulk_g2s(dst, pf + (size_t)f * NP4 + c0 + base, bytes, mbar, pol);
    }
}

// ---------------------------------------------------------------------------
// Accumulation pass: bulk-copy pipeline + softmax + (W, A) partials
// ---------------------------------------------------------------------------
__global__ __launch_bounds__(THREADS, 3) void pass_acc_kernel(const float* __restrict__ feat,
                                                              int do_update) {
    extern __shared__ char smx[];
    int b = blockIdx.x / NCH;
    int ch = blockIdx.x % NCH;
    int t = threadIdx.x;
    u32 sbase = smem_u32(smx);
    u32 mb = sbase + MBAR_O;
    float* s_g = (float*)(smx + GH_O);
    float* s_h = s_g + NK * NF;
    float4* sbuf = (float4*)smx;

    compute_gh(b, do_update, s_g, s_h);
    if (t == 0) {
        #pragma unroll
        for (int i = 0; i < NBUF; i++) mbar_init(mb + i * 8, 1);
    }
    __syncthreads();

    int c0 = (int)((long long)ch * NP4 / NCH);
    int c1 = (int)((long long)(ch + 1) * NP4 / NCH);
    int nf4 = c1 - c0;
    int nst = (nf4 + STG4 - 1) / STG4;
    const float4* pf = (const float4*)(feat + (size_t)b * NF * NPIX);
    u64p pol = mk_policy();

    if (t == 0) {
        int pre = nst < NBUF ? nst : NBUF;
        for (int s = 0; s < pre; s++) issue_stage(pf, c0, nf4, s, s, sbase, mb + s * 8, pol);
    }

    u64p g2[NKK][NF], h2[NKK];
    #pragma unroll
    for (int kk = 0; kk < NKK; kk++) {
        h2[kk] = pk2(s_h[2 * kk], s_h[2 * kk + 1]);
        #pragma unroll
        for (int f = 0; f < NF; f++)
            g2[kk][f] = pk2(s_g[(2 * kk) * NF + f], s_g[(2 * kk + 1) * NF + f]);
    }
    u64p aW2[NKK], aA2[NKK][NF];
    #pragma unroll
    for (int kk = 0; kk < NKK; kk++) {
        aW2[kk] = pk2(0.f, 0.f);
        #pragma unroll
        for (int f = 0; f < NF; f++) aA2[kk][f] = pk2(0.f, 0.f);
    }

    for (int s = 0; s < nst; s++) {
        int bufi = s % NBUF;
        u32 ph = (u32)((s / NBUF) & 1);
        mbar_wait(mb + bufi * 8, ph);
        int n = nf4 - s * STG4; if (n > STG4) n = STG4;
        const float4* bp = sbuf + bufi * NF * STG4;
        #pragma unroll
        for (int rep = 0; rep < 2; rep++) {
            int idx = t + rep * THREADS;
            if (idx < n) {
                float4 u[NF];
                #pragma unroll
                for (int f = 0; f < NF; f++) u[f] = bp[f * STG4 + idx];
                #pragma unroll
                for (int j = 0; j < 4; j++) {
                    float x[NF];
                    #pragma unroll
                    for (int f = 0; f < NF; f++)
                        x[f] = (j == 0) ? u[f].x : ((j == 1) ? u[f].y : ((j == 2) ? u[f].z : u[f].w));
                    u64p x2[NF], p2[NKK]; float r;
                    softmax_core(x, g2, h2, x2, p2, r);
                    u64p r2 = pk2(r, r);
                    #pragma unroll
                    for (int kk = 0; kk < NKK; kk++) {
                        u64p q2 = mul2(p2[kk], r2);
                        aW2[kk] = add2(aW2[kk], q2);
                        #pragma unroll
                        for (int f = 0; f < NF; f++)
                            aA2[kk][f] = fma2(q2, x2[f], aA2[kk][f]);
                    }
                }
            }
        }
        __syncthreads();   // all readers done with buffer bufi (128-thread domain)
        if (t == 0 && s + NBUF < nst)
            issue_stage(pf, c0, nf4, s + NBUF, bufi, sbase, mb + bufi * 8, pol);
    }

    // Unpack accumulators, then deterministic block reduction
    float aW[NK], aA[NK][NF];
    #pragma unroll
    for (int kk = 0; kk < NKK; kk++) {
        upk2(aW2[kk], aW[2 * kk], aW[2 * kk + 1]);
        #pragma unroll
        for (int f = 0; f < NF; f++)
            upk2(aA2[kk][f], aA[2 * kk][f], aA[2 * kk + 1][f]);
    }
    float (*smr)[NSLOT] = (float (*)[NSLOT])(smx + RED_O);
    int w = t >> 5, lane = t & 31;
    #pragma unroll
    for (int k = 0; k < NK; k++) {
        #pragma unroll
        for (int f = 0; f < NF; f++) {
            float v = aA[k][f];
            #pragma unroll
            for (int o = 16; o; o >>= 1) v += __shfl_xor_sync(0xffffffffu, v, o);
            if (lane == 0) smr[w][k * NF + f] = v;
        }
        float v = aW[k];
        #pragma unroll
        for (int o = 16; o; o >>= 1) v += __shfl_xor_sync(0xffffffffu, v, o);
        if (lane == 0) smr[w][48 + k] = v;
    }
    __syncthreads();
    if (t < NSLOT) {
        float v = 0.f;
        #pragma unroll
        for (int i = 0; i < NWARP; i++) v += smr[i][t];
        d_part[(size_t)(b * NCH + ch) * NSLOT + t] = v;
    }
}

// ---------------------------------------------------------------------------
// Final pass: pipeline + softmax + write normalized S
// ---------------------------------------------------------------------------
__global__ __launch_bounds__(THREADS, 3) void pass_out_kernel(const float* __restrict__ feat,
                                                              float* __restrict__ out) {
    extern __shared__ char smx[];
    int b = blockIdx.x / NCH;
    int ch = blockIdx.x % NCH;
    int t = threadIdx.x;
    u32 sbase = smem_u32(smx);
    u32 mb = sbase + MBAR_O;
    float* s_g = (float*)(smx + GH_O);
    float* s_h = s_g + NK * NF;
    float4* sbuf = (float4*)smx;

    compute_gh(b, 1, s_g, s_h);
    if (t == 0) {
        #pragma unroll
        for (int i = 0; i < NBUF; i++) mbar_init(mb + i * 8, 1);
    }
    __syncthreads();

    int c0 = (int)((long long)ch * NP4 / NCH);
    int c1 = (int)((long long)(ch + 1) * NP4 / NCH);
    int nf4 = c1 - c0;
    int nst = (nf4 + STG4 - 1) / STG4;
    const float4* pf = (const float4*)(feat + (size_t)b * NF * NPIX);
    float4* po = (float4*)out + (size_t)b * NK * NP4;
    u64p pol = mk_policy();

    if (t == 0) {
        int pre = nst < NBUF ? nst : NBUF;
        for (int s = 0; s < pre; s++) issue_stage(pf, c0, nf4, s, s, sbase, mb + s * 8, pol);
    }

    u64p g2[NKK][NF], h2[NKK];
    #pragma unroll
    for (int kk = 0; kk < NKK; kk++) {
        h2[kk] = pk2(s_h[2 * kk], s_h[2 * kk + 1]);
        #pragma unroll
        for (int f = 0; f < NF; f++)
            g2[kk][f] = pk2(s_g[(2 * kk) * NF + f], s_g[(2 * kk + 1) * NF + f]);
    }

    for (int s = 0; s < nst; s++) {
        int bufi = s % NBUF;
        u32 ph = (u32)((s / NBUF) & 1);
        mbar_wait(mb + bufi * 8, ph);
        int n = nf4 - s * STG4; if (n > STG4) n = STG4;
        const float4* bp = sbuf + bufi * NF * STG4;
        #pragma unroll
        for (int rep = 0; rep < 2; rep++) {
            int idx = t + rep * THREADS;
            if (idx < n) {
                float4 u[NF];
                #pragma unroll
                for (int f = 0; f < NF; f++) u[f] = bp[f * STG4 + idx];
                float wv[NK][4];
                #pragma unroll
                for (int j = 0; j < 4; j++) {
                    float x[NF];
                    #pragma unroll
                    for (int f = 0; f < NF; f++)
                        x[f] = (j == 0) ? u[f].x : ((j == 1) ? u[f].y : ((j == 2) ? u[f].z : u[f].w));
                    u64p x2[NF], p2[NKK]; float r;
                    softmax_core(x, g2, h2, x2, p2, r);
                    u64p r2 = pk2(r, r);
                    #pragma unroll
                    for (int kk = 0; kk < NKK; kk++) {
                        u64p w2 = mul2(p2[kk], r2);
                        upk2(w2, wv[2 * kk][j], wv[2 * kk + 1][j]);
                    }
                }
                int gi = c0 + s * STG4 + idx;
                #pragma unroll
                for (int k = 0; k < NK; k++) {
                    float4 o4 = make_float4(wv[k][0], wv[k][1], wv[k][2], wv[k][3]);
                    __stcs(po + k * NP4 + gi, o4);   // streaming: don't evict feat from L2
                }
            }
        }
        __syncthreads();
        if (t == 0 && s + NBUF < nst)
            issue_stage(pf, c0, nf4, s + NBUF, bufi, sbase, mb + bufi * 8, pol);
    }
}

extern "C" void kernel_launch(void* const* d_in, const int* in_sizes, int n_in,
                              void* d_out, int out_size) {
    const float* feat = (const float*)d_in[0];
    const int* idx = (const int*)d_in[1];
    float* out = (float*)d_out;

    cudaFuncSetAttribute(pass_acc_kernel, cudaFuncAttributeMaxDynamicSharedMemorySize, SMEMSZ);
    cudaFuncSetAttribute(pass_out_kernel, cudaFuncAttributeMaxDynamicSharedMemorySize, SMEMSZ);

    stats_kernel<<<NB * NF * SPLIT, 256>>>(feat);
    init_kernel<<<1, 128>>>(feat, idx);
    pass_acc_kernel<<<NB * NCH, THREADS, SMEMSZ>>>(feat, 0);        // iter 1: init g,h
    for (int i = 1; i < NITERS - 1; i++)
        pass_acc_kernel<<<NB * NCH, THREADS, SMEMSZ>>>(feat, 1);    // iters 2..11
    pass_out_kernel<<<NB * NCH, THREADS, SMEMSZ>>>(feat, out);      // iter 12 + output
}

// round 10
// speedup vs baseline: 1.0851x; 1.0851x over previous
#include <cuda_runtime.h>
#include <cstdint>

#define NB 16
#define NF 6
#define NPIX 262144
#define NP4 (NPIX / 4)   // 65536 float4 per (b,f)
#define NK 8
#define NKK 4            // packed k-pairs
#define NITERS 12
#define NCH 9            // chunks per batch -> grid 144 (~148 SMs)
#define SPLIT 8          // blocks per (b,f) in stats kernel
#define NSLOT 56         // NK*(NF+1) partial-sum slots
#define THREADS 256
#define NWARP (THREADS / 32)
#define STG4 512         // float4s per pipeline stage (per f)
#define NBUF 3           // pipeline depth

typedef unsigned long long u64p;   // packed f32x2 (and cache policy)
typedef unsigned int u32;

// Dynamic smem layout (bytes)
#define BUFB   (NBUF * NF * STG4 * 16)      // 147456
#define MBAR_O (BUFB)                       // full[3] @ +0, empty[3] @ +24 (64B region)
#define GH_O   (BUFB + 64)                  // s_g[48] + s_h[8] floats
#define RED_O  (GH_O + 224)                 // float[NWARP][NSLOT]
#define SMEMSZ (RED_O + NWARP * NSLOT * 4)  // ~149.5 KB -> 1 CTA/SM

// Scratch (static __device__ — no allocations allowed)
__device__ float d_statpart[NB * NF * SPLIT * 2];
__device__ float d_mean[NB * NF];
__device__ float d_sinv[NB * NF];
__device__ float d_g[NB * NK * NF];   // folded centroid weights (init only)
__device__ float d_h[NB * NK];        // folded centroid bias   (init only)
__device__ float d_part[NB * NCH * NSLOT];

__device__ __forceinline__ float ex2f(float x) {
    float y; asm("ex2.approx.ftz.f32 %0, %1;" : "=f"(y) : "f"(x)); return y;
}
__device__ __forceinline__ float rcpf(float x) {
    float y; asm("rcp.approx.ftz.f32 %0, %1;" : "=f"(y) : "f"(x)); return y;
}
// ---- packed f32x2 helpers (FFMA2 etc — only reachable via PTX) ----
__device__ __forceinline__ u64p pk2(float lo, float hi) {
    u64p r; asm("mov.b64 %0, {%1, %2};" : "=l"(r) : "f"(lo), "f"(hi)); return r;
}
__device__ __forceinline__ void upk2(u64p v, float& lo, float& hi) {
    asm("mov.b64 {%0, %1}, %2;" : "=f"(lo), "=f"(hi) : "l"(v));
}
__device__ __forceinline__ u64p fma2(u64p a, u64p b, u64p c) {
    u64p d; asm("fma.rn.f32x2 %0, %1, %2, %3;" : "=l"(d) : "l"(a), "l"(b), "l"(c)); return d;
}
__device__ __forceinline__ u64p add2(u64p a, u64p b) {
    u64p d; asm("add.rn.f32x2 %0, %1, %2;" : "=l"(d) : "l"(a), "l"(b)); return d;
}
__device__ __forceinline__ u64p mul2(u64p a, u64p b) {
    u64p d; asm("mul.rn.f32x2 %0, %1, %2;" : "=l"(d) : "l"(a), "l"(b)); return d;
}
// ---- smem / mbarrier / bulk-copy helpers ----
__device__ __forceinline__ u32 smem_u32(const void* p) {
    u32 a;
    asm("{ .reg .u64 t; cvta.to.shared.u64 t, %1; cvt.u32.u64 %0, t; }" : "=r"(a) : "l"(p));
    return a;
}
__device__ __forceinline__ void mbar_init(u32 mbar, u32 cnt) {
    asm volatile("mbarrier.init.shared.b64 [%0], %1;" :: "r"(mbar), "r"(cnt) : "memory");
}
__device__ __forceinline__ void mbar_arrive(u32 mbar) {
    asm volatile("mbarrier.arrive.release.cta.shared.b64 _, [%0];" :: "r"(mbar) : "memory");
}
__device__ __forceinline__ void mbar_expect_tx(u32 mbar, u32 bytes) {
    asm volatile("mbarrier.arrive.expect_tx.shared.b64 _, [%0], %1;" :: "r"(mbar), "r"(bytes) : "memory");
}
__device__ __forceinline__ void mbar_wait(u32 mbar, u32 phase) {
    asm volatile(
        "{\n\t.reg .pred P;\n"
        "WL_%=:\n\t"
        "mbarrier.try_wait.parity.acquire.cta.shared::cta.b64 P, [%0], %1, 0x989680;\n\t"
        "@P bra WD_%=;\n\t"
        "bra WL_%=;\n"
        "WD_%=:\n\t}"
        :: "r"(mbar), "r"(phase) : "memory");
}
__device__ __forceinline__ u64p mk_policy() {
    u64p p; asm("createpolicy.fractional.L2::evict_last.b64 %0, 1.0;" : "=l"(p));
    return p;
}
__device__ __forceinline__ void bulk_g2s(u32 dst, const void* src, u32 bytes,
                                         u32 mbar, u64p pol) {
    asm volatile(
        "cp.async.bulk.shared::cluster.global.mbarrier::complete_tx::bytes.L2::cache_hint "
        "[%0], [%1], %2, [%3], %4;"
        :: "r"(dst), "l"(src), "r"(bytes), "r"(mbar), "l"(pol) : "memory");
}

// ---------------------------------------------------------------------------
// Per-(b,f) sum / sumsq partials over pixels
// ---------------------------------------------------------------------------
__global__ __launch_bounds__(256) void stats_kernel(const float* __restrict__ feat) {
    int bf = blockIdx.x >> 3;     // / SPLIT
    int part = blockIdx.x & 7;    // % SPLIT
    const float4* p = ((const float4*)feat) + (size_t)bf * NP4;
    int t = threadIdx.x;
    float s = 0.f, q = 0.f;
    #pragma unroll 8
    for (int i = 0; i < 32; i++) {
        float4 v = p[part * 8192 + i * 256 + t];
        s += (v.x + v.y) + (v.z + v.w);
        q = fmaf(v.x, v.x, q); q = fmaf(v.y, v.y, q);
        q = fmaf(v.z, v.z, q); q = fmaf(v.w, v.w, q);
    }
    #pragma unroll
    for (int o = 16; o; o >>= 1) {
        s += __shfl_xor_sync(0xffffffffu, s, o);
        q += __shfl_xor_sync(0xffffffffu, q, o);
    }
    __shared__ float sm[16];
    if ((t & 31) == 0) { sm[t >> 5] = s; sm[8 + (t >> 5)] = q; }
    __syncthreads();
    if (t == 0) {
        float S = 0.f, Q = 0.f;
        #pragma unroll
        for (int i = 0; i < 8; i++) { S += sm[i]; Q += sm[8 + i]; }
        d_statpart[(bf * SPLIT + part) * 2 + 0] = S;
        d_statpart[(bf * SPLIT + part) * 2 + 1] = Q;
    }
}

// ---------------------------------------------------------------------------
// Finalize mean/invstd; gather initial centroids; fold into (g, h)
// logit_k(pixel) = sum_f u_f * g_kf + h_k   (softmax shift-invariance drops the
// per-pixel x2/T term; log2e folded so exp is a single MUFU ex2)
// ---------------------------------------------------------------------------
__global__ void init_kernel(const float* __restrict__ feat, const int* __restrict__ idx) {
    int t = threadIdx.x;  // 128 = NB*NK
    if (t < NB * NF) {
        float S = 0.f, Q = 0.f;
        for (int i = 0; i < SPLIT; i++) {
            S += d_statpart[(t * SPLIT + i) * 2 + 0];
            Q += d_statpart[(t * SPLIT + i) * 2 + 1];
        }
        float mean = S * (1.f / (float)NPIX);
        float var = (Q - (float)NPIX * mean * mean) * (1.f / (float)(NPIX - 1));
        var = fmaxf(var, 0.f);
        float sd = sqrtf(var);
        d_mean[t] = mean;
        d_sinv[t] = 1.f / fmaxf(sd, 1e-6f);
    }
    __syncthreads();
    int b = t >> 3;
    int n = idx[t];
    const float alpha = 1.4426950408889634f / 0.15f;  // log2(e)/TEMP
    float c2 = 0.f;
    float g[NF];
    #pragma unroll
    for (int f = 0; f < NF; f++) {
        float u = feat[(size_t)(b * NF + f) * NPIX + n];
        float c = (u - d_mean[b * NF + f]) * d_sinv[b * NF + f];
        c2 = fmaf(c, c, c2);
        g[f] = 2.f * alpha * d_sinv[b * NF + f] * c;
    }
    float h = -alpha * c2;
    #pragma unroll
    for (int f = 0; f < NF; f++) {
        h -= d_mean[b * NF + f] * g[f];
        d_g[t * NF + f] = g[f];
    }
    d_h[t] = h;
}

// ---------------------------------------------------------------------------
// Per-block preamble: centroid update from previous pass's partials
// (redundant per block — the launch boundary is the grid sync).
// ---------------------------------------------------------------------------
__device__ __forceinline__ void compute_gh(int b, int do_update, float* s_g, float* s_h) {
    int t = threadIdx.x;
    if (t < NK) {
        int k = t;
        float gg[NF], hh;
        if (do_update) {
            float W = 0.f, A[NF] = {0.f, 0.f, 0.f, 0.f, 0.f, 0.f};
            for (int i = 0; i < NCH; i++) {
                const float* pp = d_part + (size_t)(b * NCH + i) * NSLOT;
                W += pp[48 + k];
                #pragma unroll
                for (int f = 0; f < NF; f++) A[f] += pp[k * NF + f];
            }
            float rW = 1.f / fmaxf(W, 1e-6f);
            const float alpha = 1.4426950408889634f / 0.15f;
            float c2 = 0.f;
            #pragma unroll
            for (int f = 0; f < NF; f++) {
                float si = d_sinv[b * NF + f];
                // C_kf = s_f * (A_f - m_f*W) / clip(W, EPS)  (matches reference)
                float c = si * (A[f] - d_mean[b * NF + f] * W) * rW;
                c2 = fmaf(c, c, c2);
                gg[f] = 2.f * alpha * si * c;
            }
            hh = -alpha * c2;
            #pragma unroll
            for (int f = 0; f < NF; f++) hh -= d_mean[b * NF + f] * gg[f];
        } else {
            #pragma unroll
            for (int f = 0; f < NF; f++) gg[f] = d_g[(b * NK + k) * NF + f];
            hh = d_h[b * NK + k];
        }
        #pragma unroll
        for (int f = 0; f < NF; f++) s_g[k * NF + f] = gg[f];
        s_h[k] = hh;
    }
}

// ---------------------------------------------------------------------------
// Packed softmax core
// ---------------------------------------------------------------------------
__device__ __forceinline__ void softmax_core(const float x[NF],
                                             const u64p g2[NKK][NF], const u64p h2[NKK],
                                             u64p x2[NF], u64p p2[NKK], float& r) {
    #pragma unroll
    for (int f = 0; f < NF; f++) x2[f] = pk2(x[f], x[f]);
    u64p l2[NKK];
    #pragma unroll
    for (int kk = 0; kk < NKK; kk++) l2[kk] = fma2(x2[0], g2[kk][0], h2[kk]);
    #pragma unroll
    for (int f = 1; f < NF; f++)
        #pragma unroll
        for (int kk = 0; kk < NKK; kk++) l2[kk] = fma2(x2[f], g2[kk][f], l2[kk]);
    float l[NK];
    #pragma unroll
    for (int kk = 0; kk < NKK; kk++) upk2(l2[kk], l[2 * kk], l[2 * kk + 1]);
    float m = l[0];
    #pragma unroll
    for (int k = 1; k < NK; k++) m = fmaxf(m, l[k]);
    u64p mn2 = pk2(-m, -m);
    float p[NK];
    #pragma unroll
    for (int kk = 0; kk < NKK; kk++) {
        u64p e = add2(l2[kk], mn2);
        float a, c; upk2(e, a, c);
        p[2 * kk] = ex2f(a);
        p[2 * kk + 1] = ex2f(c);
    }
    #pragma unroll
    for (int kk = 0; kk < NKK; kk++) p2[kk] = pk2(p[2 * kk], p[2 * kk + 1]);
    u64p s2 = add2(add2(p2[0], p2[1]), add2(p2[2], p2[3]));
    float sl, sh; upk2(s2, sl, sh);
    r = rcpf(sl + sh);
}

// ---------------------------------------------------------------------------
// Stage issue: elected thread prefetches stage s of this chunk into buffer bufi
// ---------------------------------------------------------------------------
__device__ __forceinline__ void issue_stage(const float4* pf, int c0, int nf4, int s,
                                            int bufi, u32 sbase, u32 mbar, u64p pol) {
    int base = s * STG4;
    int n = nf4 - base; if (n > STG4) n = STG4;
    u32 bytes = (u32)n * 16u;
    mbar_expect_tx(mbar, bytes * NF);
    #pragma unroll
    for (int f = 0; f < NF; f++) {
        u32 dst = sbase + (u32)((bufi * NF + f) * STG4) * 16u;
        bulk_g2s(dst, pf + (size_t)f * NP4 + c0 + base, bytes, mbar, pol);
    }
}

// ---------------------------------------------------------------------------
// Accumulation pass: decoupled full/empty pipeline + softmax + (W, A) partials
// ---------------------------------------------------------------------------
__global__ __launch_bounds__(THREADS, 1) void pass_acc_kernel(const float* __restrict__ feat,
                                                              int do_update) {
    extern __shared__ char smx[];
    int b = blockIdx.x / NCH;
    int ch = blockIdx.x % NCH;
    int t = threadIdx.x;
    int warp = t >> 5, lane = t & 31;
    u32 sbase = smem_u32(smx);
    u32 mbF = sbase + MBAR_O;        // full[i] = mbF + i*8
    u32 mbE = sbase + MBAR_O + 24;   // empty[i] = mbE + i*8
    float* s_g = (float*)(smx + GH_O);
    float* s_h = s_g + NK * NF;
    float4* sbuf = (float4*)smx;

    compute_gh(b, do_update, s_g, s_h);
    if (t == 0) {
        #pragma unroll
        for (int i = 0; i < NBUF; i++) { mbar_init(mbF + i * 8, 1); mbar_init(mbE + i * 8, NWARP); }
    }
    __syncthreads();

    int c0 = ch * NP4 / NCH;
    int c1 = (ch + 1) * NP4 / NCH;
    int nf4 = c1 - c0;
    int nst = (nf4 + STG4 - 1) / STG4;
    const float4* pf = (const float4*)(feat + (size_t)b * NF * NPIX);
    u64p pol = mk_policy();

    if (t == 0)
        for (int s = 0; s < NBUF; s++) issue_stage(pf, c0, nf4, s, s, sbase, mbF + s * 8, pol);

    u64p g2[NKK][NF], h2[NKK];
    #pragma unroll
    for (int kk = 0; kk < NKK; kk++) {
        h2[kk] = pk2(s_h[2 * kk], s_h[2 * kk + 1]);
        #pragma unroll
        for (int f = 0; f < NF; f++)
            g2[kk][f] = pk2(s_g[(2 * kk) * NF + f], s_g[(2 * kk + 1) * NF + f]);
    }
    u64p aW2[NKK], aA2[NKK][NF];
    #pragma unroll
    for (int kk = 0; kk < NKK; kk++) {
        aW2[kk] = pk2(0.f, 0.f);
        #pragma unroll
        for (int f = 0; f < NF; f++) aA2[kk][f] = pk2(0.f, 0.f);
    }

    for (int s = 0; s < nst; s++) {
        int bufi = s % NBUF;
        u32 ph = (u32)((s / NBUF) & 1);
        mbar_wait(mbF + bufi * 8, ph);            // data ready (this warp only)
        int n = nf4 - s * STG4; if (n > STG4) n = STG4;
        const float4* bp = sbuf + bufi * NF * STG4;
        #pragma unroll
        for (int rep = 0; rep < 2; rep++) {
            int idx = t + rep * THREADS;
            if (idx < n) {
                float4 u[NF];
                #pragma unroll
                for (int f = 0; f < NF; f++) u[f] = bp[f * STG4 + idx];
                #pragma unroll
                for (int j = 0; j < 4; j++) {
                    float x[NF];
                    #pragma unroll
                    for (int f = 0; f < NF; f++)
                        x[f] = (j == 0) ? u[f].x : ((j == 1) ? u[f].y : ((j == 2) ? u[f].z : u[f].w));
                    u64p x2[NF], p2[NKK]; float r;
                    softmax_core(x, g2, h2, x2, p2, r);
                    u64p r2 = pk2(r, r);
                    #pragma unroll
                    for (int kk = 0; kk < NKK; kk++) {
                        u64p q2 = mul2(p2[kk], r2);
                        aW2[kk] = add2(aW2[kk], q2);
                        #pragma unroll
                        for (int f = 0; f < NF; f++)
                            aA2[kk][f] = fma2(q2, x2[f], aA2[kk][f]);
                    }
                }
            }
        }
        // this warp is done with buffer bufi — release it and move on (no CTA sync)
        __syncwarp();
        if (lane == 0) mbar_arrive(mbE + bufi * 8);
        // producer warp re-fills the buffer once all 8 warps released it
        if (warp == 0 && s + NBUF < nst) {
            mbar_wait(mbE + bufi * 8, (u32)((s / NBUF) & 1));
            if (lane == 0) issue_stage(pf, c0, nf4, s + NBUF, bufi, sbase, mbF + bufi * 8, pol);
        }
    }

    // Unpack accumulators, then deterministic block reduction
    float aW[NK], aA[NK][NF];
    #pragma unroll
    for (int kk = 0; kk < NKK; kk++) {
        upk2(aW2[kk], aW[2 * kk], aW[2 * kk + 1]);
        #pragma unroll
        for (int f = 0; f < NF; f++)
            upk2(aA2[kk][f], aA[2 * kk][f], aA[2 * kk + 1][f]);
    }
    float (*smr)[NSLOT] = (float (*)[NSLOT])(smx + RED_O);
    #pragma unroll
    for (int k = 0; k < NK; k++) {
        #pragma unroll
        for (int f = 0; f < NF; f++) {
            float v = aA[k][f];
            #pragma unroll
            for (int o = 16; o; o >>= 1) v += __shfl_xor_sync(0xffffffffu, v, o);
            if (lane == 0) smr[warp][k * NF + f] = v;
        }
        float v = aW[k];
        #pragma unroll
        for (int o = 16; o; o >>= 1) v += __shfl_xor_sync(0xffffffffu, v, o);
        if (lane == 0) smr[warp][48 + k] = v;
    }
    __syncthreads();
    if (t < NSLOT) {
        float v = 0.f;
        #pragma unroll
        for (int i = 0; i < NWARP; i++) v += smr[i][t];
        d_part[(size_t)(b * NCH + ch) * NSLOT + t] = v;
    }
}

// ---------------------------------------------------------------------------
// Final pass: decoupled pipeline + softmax + write normalized S
// ---------------------------------------------------------------------------
__global__ __launch_bounds__(THREADS, 1) void pass_out_kernel(const float* __restrict__ feat,
                                                              float* __restrict__ out) {
    extern __shared__ char smx[];
    int b = blockIdx.x / NCH;
    int ch = blockIdx.x % NCH;
    int t = threadIdx.x;
    int warp = t >> 5, lane = t & 31;
    u32 sbase = smem_u32(smx);
    u32 mbF = sbase + MBAR_O;
    u32 mbE = sbase + MBAR_O + 24;
    float* s_g = (float*)(smx + GH_O);
    float* s_h = s_g + NK * NF;
    float4* sbuf = (float4*)smx;

    compute_gh(b, 1, s_g, s_h);
    if (t == 0) {
        #pragma unroll
        for (int i = 0; i < NBUF; i++) { mbar_init(mbF + i * 8, 1); mbar_init(mbE + i * 8, NWARP); }
    }
    __syncthreads();

    int c0 = ch * NP4 / NCH;
    int c1 = (ch + 1) * NP4 / NCH;
    int nf4 = c1 - c0;
    int nst = (nf4 + STG4 - 1) / STG4;
    const float4* pf = (const float4*)(feat + (size_t)b * NF * NPIX);
    float4* po = (float4*)out + (size_t)b * NK * NP4;
    u64p pol = mk_policy();

    if (t == 0)
        for (int s = 0; s < NBUF; s++) issue_stage(pf, c0, nf4, s, s, sbase, mbF + s * 8, pol);

    u64p g2[NKK][NF], h2[NKK];
    #pragma unroll
    for (int kk = 0; kk < NKK; kk++) {
        h2[kk] = pk2(s_h[2 * kk], s_h[2 * kk + 1]);
        #pragma unroll
        for (int f = 0; f < NF; f++)
            g2[kk][f] = pk2(s_g[(2 * kk) * NF + f], s_g[(2 * kk + 1) * NF + f]);
    }

    for (int s = 0; s < nst; s++) {
        int bufi = s % NBUF;
        u32 ph = (u32)((s / NBUF) & 1);
        mbar_wait(mbF + bufi * 8, ph);
        int n = nf4 - s * STG4; if (n > STG4) n = STG4;
        const float4* bp = sbuf + bufi * NF * STG4;
        #pragma unroll
        for (int rep = 0; rep < 2; rep++) {
            int idx = t + rep * THREADS;
            if (idx < n) {
                float4 u[NF];
                #pragma unroll
                for (int f = 0; f < NF; f++) u[f] = bp[f * STG4 + idx];
                float wv[NK][4];
                #pragma unroll
                for (int j = 0; j < 4; j++) {
                    float x[NF];
                    #pragma unroll
                    for (int f = 0; f < NF; f++)
                        x[f] = (j == 0) ? u[f].x : ((j == 1) ? u[f].y : ((j == 2) ? u[f].z : u[f].w));
                    u64p x2[NF], p2[NKK]; float r;
                    softmax_core(x, g2, h2, x2, p2, r);
                    u64p r2 = pk2(r, r);
                    #pragma unroll
                    for (int kk = 0; kk < NKK; kk++) {
                        u64p w2 = mul2(p2[kk], r2);
                        upk2(w2, wv[2 * kk][j], wv[2 * kk + 1][j]);
                    }
                }
                int gi = c0 + s * STG4 + idx;
                #pragma unroll
                for (int k = 0; k < NK; k++) {
                    float4 o4 = make_float4(wv[k][0], wv[k][1], wv[k][2], wv[k][3]);
                    __stcs(po + k * NP4 + gi, o4);   // streaming: don't evict feat from L2
                }
            }
        }
        __syncwarp();
        if (lane == 0) mbar_arrive(mbE + bufi * 8);
        if (warp == 0 && s + NBUF < nst) {
            mbar_wait(mbE + bufi * 8, (u32)((s / NBUF) & 1));
            if (lane == 0) issue_stage(pf, c0, nf4, s + NBUF, bufi, sbase, mbF + bufi * 8, pol);
        }
    }
}

extern "C" void kernel_launch(void* const* d_in, const int* in_sizes, int n_in,
                              void* d_out, int out_size) {
    const float* feat = (const float*)d_in[0];
    const int* idx = (const int*)d_in[1];
    float* out = (float*)d_out;

    cudaFuncSetAttribute(pass_acc_kernel, cudaFuncAttributeMaxDynamicSharedMemorySize, SMEMSZ);
    cudaFuncSetAttribute(pass_out_kernel, cudaFuncAttributeMaxDynamicSharedMemorySize, SMEMSZ);

    stats_kernel<<<NB * NF * SPLIT, 256>>>(feat);
    init_kernel<<<1, 128>>>(feat, idx);
    pass_acc_kernel<<<NB * NCH, THREADS, SMEMSZ>>>(feat, 0);        // iter 1: init g,h
    for (int i = 1; i < NITERS - 1; i++)
        pass_acc_kernel<<<NB * NCH, THREADS, SMEMSZ>>>(feat, 1);    // iters 2..11
    pass_out_kernel<<<NB * NCH, THREADS, SMEMSZ>>>(feat, out);      // iter 12 + output
}